// round 10
// baseline (speedup 1.0000x reference)
#include <cuda_runtime.h>
#include <math.h>

// Problem constants
#define TSTEPS 64
#define BATCH  32
#define NH     512
#define NH2    1024
#define VOCAB  32000
#define RROWS  (TSTEPS*BATCH)   // 2048

// ---------------------------------------------------------------------------
// Scratch (static device globals; no allocation anywhere)
// ---------------------------------------------------------------------------
__device__ __align__(16) float g_X[RROWS*NH];                 // gathered embeddings   (4 MB)
__device__ __align__(16) float g_Xpre[RROWS*NH2];             // X @ W0[:512,:]        (8 MB)
__device__ __align__(16) float g_states[8][BATCH*NH];         // node accumulators
__device__ __align__(16) float g_h[BATCH*NH];                 // current hidden
__device__ __align__(16) float g_hid[RROWS*NH];               // all hiddens           (4 MB)
__device__ __align__(16) float g_logits[(size_t)RROWS*VOCAB]; // logits scratch        (262 MB)

// ---------------------------------------------------------------------------
// Small helpers
// ---------------------------------------------------------------------------
__global__ __launch_bounds__(256) void kInitH(const float* __restrict__ h0) {
    int idx = blockIdx.x * 256 + threadIdx.x;
    if (idx < BATCH*NH) g_h[idx] = h0[idx];
}

// One block per (t,b) row; 128 threads x float4 = 512 floats
__global__ __launch_bounds__(128) void kEmbed(const int* __restrict__ ids,
                                              const float* __restrict__ emb) {
    int r = blockIdx.x;
    int row = ids[r];
    const float4* src = reinterpret_cast<const float4*>(emb + (size_t)row * NH);
    float4* dst = reinterpret_cast<float4*>(g_X + (size_t)r * NH);
    dst[threadIdx.x] = src[threadIdx.x];
}

// ---------------------------------------------------------------------------
// Xpre = g_X[2048,512] @ W0[0:512, 0:1024]   (NN SGEMM, 64x64 tile, 4x4 micro)
// ---------------------------------------------------------------------------
__global__ __launch_bounds__(256) void kXpreGemm(const float* __restrict__ W0) {
    __shared__ __align__(16) float As[16][64];
    __shared__ __align__(16) float Bs[16][64];
    const int m0 = blockIdx.y * 64, n0 = blockIdx.x * 64;
    const int tid = threadIdx.x, tx = tid & 15, ty = tid >> 4;
    const int am = tid >> 2, ak4 = (tid & 3) * 4;   // A load: row am, k offset ak4
    const int bk = tid >> 4, bn4 = (tid & 15) * 4;  // B load: k row bk, n offset bn4
    float acc[4][4];
#pragma unroll
    for (int i = 0; i < 4; i++)
#pragma unroll
        for (int j = 0; j < 4; j++) acc[i][j] = 0.f;

    for (int k0 = 0; k0 < NH; k0 += 16) {
        float4 av = *reinterpret_cast<const float4*>(g_X + (size_t)(m0+am)*NH + k0 + ak4);
        As[ak4+0][am] = av.x; As[ak4+1][am] = av.y; As[ak4+2][am] = av.z; As[ak4+3][am] = av.w;
        *reinterpret_cast<float4*>(&Bs[bk][bn4]) =
            *reinterpret_cast<const float4*>(W0 + (size_t)(k0+bk)*NH2 + n0 + bn4);
        __syncthreads();
#pragma unroll
        for (int kk = 0; kk < 16; kk++) {
            float4 a = *reinterpret_cast<float4*>(&As[kk][ty*4]);
            float4 b = *reinterpret_cast<float4*>(&Bs[kk][tx*4]);
            float aa[4] = {a.x,a.y,a.z,a.w}, bb[4] = {b.x,b.y,b.z,b.w};
#pragma unroll
            for (int i = 0; i < 4; i++)
#pragma unroll
                for (int j = 0; j < 4; j++) acc[i][j] += aa[i]*bb[j];
        }
        __syncthreads();
    }
#pragma unroll
    for (int i = 0; i < 4; i++) {
        float4 st = make_float4(acc[i][0], acc[i][1], acc[i][2], acc[i][3]);
        *reinterpret_cast<float4*>(g_Xpre + (size_t)(m0+ty*4+i)*NH2 + n0 + tx*4) = st;
    }
}

// ---------------------------------------------------------------------------
// W0 stage: s0 = h + sigmoid(c0)*(tanh(h0) - h),  [c0|h0] = Xpre[t] + h @ W0[512:,:]
// Block: all 32 rows x 16 d's (paired c/h columns). 128 threads, 4 rows x (c,h) per thread.
// ---------------------------------------------------------------------------
__global__ __launch_bounds__(128) void kNode0(const float* __restrict__ W0, int t) {
    __shared__ __align__(16) float As[16][32];
    __shared__ __align__(16) float Bs[16][32];
    const int d0 = blockIdx.x * 16;
    const int tid = threadIdx.x, tx = tid & 15, ty = tid >> 4;  // ty: 0..7
    const int am = tid >> 2, ak4 = (tid & 3) * 4;               // am: 0..31
    const int bk = tid >> 3, bc4 = (tid & 7) * 4;               // bk: 0..15
    const float* Wh = W0 + (size_t)NH * NH2;                    // rows 512..1023
    const int ncol = (bc4 < 16) ? (d0 + bc4) : (NH + d0 + (bc4 - 16));
    float accC[4] = {0,0,0,0}, accH[4] = {0,0,0,0};

    for (int k0 = 0; k0 < NH; k0 += 16) {
        float4 av = *reinterpret_cast<const float4*>(g_h + am*NH + k0 + ak4);
        As[ak4+0][am] = av.x; As[ak4+1][am] = av.y; As[ak4+2][am] = av.z; As[ak4+3][am] = av.w;
        *reinterpret_cast<float4*>(&Bs[bk][bc4]) =
            *reinterpret_cast<const float4*>(Wh + (size_t)(k0+bk)*NH2 + ncol);
        __syncthreads();
#pragma unroll
        for (int kk = 0; kk < 16; kk++) {
            float4 a = *reinterpret_cast<float4*>(&As[kk][ty*4]);
            float wc = Bs[kk][tx], wh = Bs[kk][16+tx];
            accC[0] += a.x*wc; accC[1] += a.y*wc; accC[2] += a.z*wc; accC[3] += a.w*wc;
            accH[0] += a.x*wh; accH[1] += a.y*wh; accH[2] += a.z*wh; accH[3] += a.w*wh;
        }
        __syncthreads();
    }
    const int d = d0 + tx;
    const float* xp = g_Xpre + (size_t)(t*BATCH)*NH2;
#pragma unroll
    for (int q = 0; q < 4; q++) {
        int b = ty*4 + q;
        float cc = accC[q] + xp[b*NH2 + d];
        float hh = accH[q] + xp[b*NH2 + NH + d];
        float hp = g_h[b*NH + d];
        float sg = 1.f / (1.f + expf(-cc));
        g_states[0][b*NH + d] = hp + sg * (tanhf(hh) - hp);
    }
}

// ---------------------------------------------------------------------------
// Edge stage i: for each j>i: [c|h] = (states[i]/cnt) @ Ws[i,j];
//   s = sp + sigmoid(c)*(act_j(h) - sp);  states[j] (=, i==0) / (+=, i>0)
// OPS: j=1,4 tanh; j=2,5 relu; j=3,6 sigmoid; j=7 identity
// ---------------------------------------------------------------------------
__global__ __launch_bounds__(128) void kEdge(const float* __restrict__ Ws, int i) {
    __shared__ __align__(16) float As[16][32];
    __shared__ __align__(16) float Bs[16][32];
    const int j  = i + 1 + blockIdx.y;
    const int d0 = blockIdx.x * 16;
    const float inv = (i == 0) ? 1.f : 1.f / (float)i;   // counts: 1 for node 0, i for node i>=1
    const float* W = Ws + (size_t)(i*8 + j) * NH * NH2;
    const float* S = g_states[i];
    const int tid = threadIdx.x, tx = tid & 15, ty = tid >> 4;
    const int am = tid >> 2, ak4 = (tid & 3) * 4;
    const int bk = tid >> 3, bc4 = (tid & 7) * 4;
    const int ncol = (bc4 < 16) ? (d0 + bc4) : (NH + d0 + (bc4 - 16));
    float accC[4] = {0,0,0,0}, accH[4] = {0,0,0,0};

    for (int k0 = 0; k0 < NH; k0 += 16) {
        float4 av = *reinterpret_cast<const float4*>(S + am*NH + k0 + ak4);
        As[ak4+0][am] = av.x; As[ak4+1][am] = av.y; As[ak4+2][am] = av.z; As[ak4+3][am] = av.w;
        *reinterpret_cast<float4*>(&Bs[bk][bc4]) =
            *reinterpret_cast<const float4*>(W + (size_t)(k0+bk)*NH2 + ncol);
        __syncthreads();
#pragma unroll
        for (int kk = 0; kk < 16; kk++) {
            float4 a = *reinterpret_cast<float4*>(&As[kk][ty*4]);
            float wc = Bs[kk][tx], wh = Bs[kk][16+tx];
            accC[0] += a.x*wc; accC[1] += a.y*wc; accC[2] += a.z*wc; accC[3] += a.w*wc;
            accH[0] += a.x*wh; accH[1] += a.y*wh; accH[2] += a.z*wh; accH[3] += a.w*wh;
        }
        __syncthreads();
    }
    const int d = d0 + tx;
#pragma unroll
    for (int q = 0; q < 4; q++) {
        int b = ty*4 + q;
        float sp = S[b*NH + d] * inv;       // normalized s_prev
        float cc = accC[q] * inv;           // scale folded out of the GEMM (linear)
        float hh = accH[q] * inv;
        float act;
        if (j == 1 || j == 4)       act = tanhf(hh);
        else if (j == 2 || j == 5)  act = fmaxf(hh, 0.f);
        else if (j == 3 || j == 6)  act = 1.f / (1.f + expf(-hh));
        else                        act = hh;   // j == 7 identity
        float sg = 1.f / (1.f + expf(-cc));
        float s  = sp + sg * (act - sp);
        float* dst = &g_states[j][b*NH + d];
        if (i == 0) *dst = s;
        else        *dst = *dst + s;
    }
}

// ---------------------------------------------------------------------------
// h_new = mean_{j=1..7}( states[j] / j ); store to g_h, g_hid[t], optionally last_h out
// ---------------------------------------------------------------------------
__global__ __launch_bounds__(256) void kAvg(int t, float* __restrict__ lastOut) {
    int idx = blockIdx.x * 256 + threadIdx.x;
    if (idx >= BATCH*NH) return;
    float s = 0.f;
#pragma unroll
    for (int j = 1; j < 8; j++) s += g_states[j][idx] * (1.f / (float)j);
    s *= (1.f / 7.f);
    g_h[idx] = s;
    g_hid[(size_t)t * BATCH * NH + idx] = s;
    if (lastOut) lastOut[idx] = s;
}

// ---------------------------------------------------------------------------
// Decoder: logits[r,v] = g_hid[r,:] . emb[v,:] + bias[v]   (NT SGEMM 64x64, 4x4 micro)
// ---------------------------------------------------------------------------
__global__ __launch_bounds__(256) void kDecGemm(const float* __restrict__ emb,
                                                const float* __restrict__ bias) {
    __shared__ __align__(16) float As[16][64];
    __shared__ __align__(16) float Bs[16][64];
    const int m0 = blockIdx.y * 64, n0 = blockIdx.x * 64;
    const int tid = threadIdx.x, tx = tid & 15, ty = tid >> 4;
    const int am = tid >> 2, ak4 = (tid & 3) * 4;
    const int bn = tid >> 2, bk4 = (tid & 3) * 4;
    float acc[4][4];
#pragma unroll
    for (int i = 0; i < 4; i++)
#pragma unroll
        for (int j = 0; j < 4; j++) acc[i][j] = 0.f;

    for (int k0 = 0; k0 < NH; k0 += 16) {
        float4 av = *reinterpret_cast<const float4*>(g_hid + (size_t)(m0+am)*NH + k0 + ak4);
        As[ak4+0][am] = av.x; As[ak4+1][am] = av.y; As[ak4+2][am] = av.z; As[ak4+3][am] = av.w;
        float4 bv = *reinterpret_cast<const float4*>(emb + (size_t)(n0+bn)*NH + k0 + bk4);
        Bs[bk4+0][bn] = bv.x; Bs[bk4+1][bn] = bv.y; Bs[bk4+2][bn] = bv.z; Bs[bk4+3][bn] = bv.w;
        __syncthreads();
#pragma unroll
        for (int kk = 0; kk < 16; kk++) {
            float4 a = *reinterpret_cast<float4*>(&As[kk][ty*4]);
            float4 b = *reinterpret_cast<float4*>(&Bs[kk][tx*4]);
            float aa[4] = {a.x,a.y,a.z,a.w}, bb[4] = {b.x,b.y,b.z,b.w};
#pragma unroll
            for (int i = 0; i < 4; i++)
#pragma unroll
                for (int j = 0; j < 4; j++) acc[i][j] += aa[i]*bb[j];
        }
        __syncthreads();
    }
    float4 bz = *reinterpret_cast<const float4*>(bias + n0 + tx*4);
#pragma unroll
    for (int i = 0; i < 4; i++) {
        int row = m0 + ty*4 + i;
        float4 st = make_float4(acc[i][0]+bz.x, acc[i][1]+bz.y, acc[i][2]+bz.z, acc[i][3]+bz.w);
        *reinterpret_cast<float4*>(g_logits + (size_t)row*VOCAB + n0 + tx*4) = st;
    }
}

// ---------------------------------------------------------------------------
// Online log-softmax per row: one pass max+scaled-sum, one pass write.
// ---------------------------------------------------------------------------
__global__ __launch_bounds__(256) void kSoftmax(float* __restrict__ out) {
    const int r = blockIdx.x;
    const float* __restrict__ row = g_logits + (size_t)r * VOCAB;
    float m = -INFINITY, s = 0.f;
    for (int v = threadIdx.x; v < VOCAB; v += 256) {
        float x = row[v];
        if (x > m) { s = s * expf(m - x) + 1.f; m = x; }
        else       { s += expf(x - m); }
    }
    __shared__ float sm[256], ss[256];
    sm[threadIdx.x] = m; ss[threadIdx.x] = s;
    __syncthreads();
    for (int st = 128; st > 0; st >>= 1) {
        if (threadIdx.x < st) {
            float m2 = sm[threadIdx.x + st], s2 = ss[threadIdx.x + st];
            float m1 = sm[threadIdx.x],      s1 = ss[threadIdx.x];
            float M = fmaxf(m1, m2);
            sm[threadIdx.x] = M;
            ss[threadIdx.x] = s1 * expf(m1 - M) + s2 * expf(m2 - M);
        }
        __syncthreads();
    }
    const float lse = sm[0] + logf(ss[0]);
    float* __restrict__ orow = out + (size_t)r * VOCAB;
    for (int v = threadIdx.x; v < VOCAB; v += 256)
        orow[v] = row[v] - lse;
}

// ---------------------------------------------------------------------------
// Launch: embedding + x-part precompute, 64 sequential steps (9 kernels each),
// decoder GEMM, fused log-softmax. Graph-capturable: kernel launches only.
// ---------------------------------------------------------------------------
extern "C" void kernel_launch(void* const* d_in, const int* in_sizes, int n_in,
                              void* d_out, int out_size) {
    const int*   ids  = (const int*)  d_in[0];   // [64,32]
    const float* h0   = (const float*)d_in[1];   // [1,32,512]
    const float* emb  = (const float*)d_in[2];   // [32000,512]
    const float* W0   = (const float*)d_in[3];   // [1024,1024]
    const float* Ws   = (const float*)d_in[4];   // [8,8,512,1024]
    const float* bias = (const float*)d_in[5];   // [32000]
    float* out = (float*)d_out;                  // [64,32,32000] ++ [1,32,512]

    kInitH<<<64, 256>>>(h0);
    kEmbed<<<RROWS, 128>>>(ids, emb);
    kXpreGemm<<<dim3(NH2/64, RROWS/64), 256>>>(W0);

    for (int t = 0; t < TSTEPS; t++) {
        kNode0<<<NH/16, 128>>>(W0, t);
        for (int i = 0; i < 7; i++)
            kEdge<<<dim3(NH/16, 7 - i), 128>>>(Ws, i);
        kAvg<<<64, 256>>>(t, (t == TSTEPS-1) ? (out + (size_t)RROWS * VOCAB) : nullptr);
    }

    kDecGemm<<<dim3(VOCAB/64, RROWS/64), 256>>>(emb, bias);
    kSoftmax<<<RROWS, 256>>>(out);
}